// round 17
// baseline (speedup 1.0000x reference)
#include <cuda_runtime.h>
#include <cuda_fp16.h>
#include <cstdint>

#define N_ROWS   65536
#define K_CENT   512
#define D_DIM    1024
#define TILE_M   128
#define CH_N     256          // centers per chunk
#define NCHUNK   2
#define KSLAB    32
#define NSLABS   (D_DIM / KSLAB)   // 32
#define TAU_F    0.1f
#define EPS_F    1e-8f

// Normalized centers in fp16 (1/||c|| folded), row-major [K_CENT][D_DIM]
__device__ __align__(16) __half g_cbf[K_CENT * D_DIM];
// Normalized embeddings in fp16 with 1/(||e||*tau) folded, [N_ROWS][D_DIM]
__device__ __align__(16) __half g_ebf[(size_t)N_ROWS * D_DIM];
// Per-chunk partial softmax stats
__device__ float g_pm[NCHUNK * N_ROWS];
__device__ float g_ps[NCHUNK * N_ROWS];
__device__ float g_plv[NCHUNK * N_ROWS];
// Per-mtile completion counters (self-resetting each replay)
__device__ int g_cnt[N_ROWS / TILE_M];

// ---------------- helpers ----------------
__device__ __forceinline__ uint32_t smem_u32(const void* p) {
    uint32_t a;
    asm("{ .reg .u64 t; cvta.to.shared.u64 t, %1; cvt.u32.u64 %0, t; }" : "=r"(a) : "l"(p));
    return a;
}
// SW64 swizzle for 64B rows
#define SWZ64(o) ((o) ^ ((((uint32_t)(o)) >> 3) & 0x30u))

__device__ __forceinline__ void cp16(uint32_t dst, const void* src) {
    asm volatile("cp.async.cg.shared.global [%0], [%1], 16;"
                 :: "r"(dst), "l"(__cvta_generic_to_global(src)) : "memory");
}

#define MBARRIER_INIT(addr, cnt) \
    asm volatile("mbarrier.init.shared.b64 [%0], %1;" :: "r"(addr), "r"((uint32_t)(cnt)) : "memory")
#define MBARRIER_ARRIVE(addr) \
    asm volatile("mbarrier.arrive.shared.b64 _, [%0];" :: "r"(addr) : "memory")
// arrive on mbar once this thread's prior cp.async ops complete (counts vs init count)
#define CP_MBAR_ARRIVE(addr) \
    asm volatile("cp.async.mbarrier.arrive.noinc.shared.b64 [%0];" :: "r"(addr) : "memory")

#define MBARRIER_WAIT_PARITY(mbar_smem_addr, phase_parity) do { \
    uint32_t _mbar = (uint32_t)(mbar_smem_addr); \
    uint32_t _parity = (uint32_t)(phase_parity); \
    uint32_t _done; \
    asm volatile( \
        "{\n\t" \
        ".reg .pred p;\n\t" \
        "mbarrier.try_wait.parity.acquire.cta.shared::cta.b64 p, [%1], %2;\n\t" \
        "selp.b32 %0, 1, 0, p;\n\t" \
        "}" \
        : "=r"(_done) : "r"(_mbar), "r"(_parity) : "memory"); \
    if (!_done) { \
        asm volatile( \
            "{\n\t" \
            ".reg .pred P1;\n\t" \
            "WAIT_LOOP_%=:\n\t" \
            "mbarrier.try_wait.parity.acquire.cta.shared::cta.b64 P1, [%0], %1, 0x989680;\n\t" \
            "@P1 bra.uni WAIT_DONE_%=;\n\t" \
            "bra.uni WAIT_LOOP_%=;\n\t" \
            "WAIT_DONE_%=:\n\t" \
            "}" \
            :: "r"(_mbar), "r"(_parity) : "memory"); \
    } \
} while (0)

__device__ __forceinline__ void ldsm4(uint32_t* r, uint32_t addr) {
    asm volatile("ldmatrix.sync.aligned.m8n8.x4.shared.b16 {%0,%1,%2,%3}, [%4];"
                 : "=r"(r[0]), "=r"(r[1]), "=r"(r[2]), "=r"(r[3]) : "r"(addr));
}

// fp16-accumulate HMMA: D(2 regs f16x2) = A(4) * B(2) + D
__device__ __forceinline__ void mma_h(uint32_t* d, const uint32_t* a,
                                      uint32_t b0, uint32_t b1) {
    asm volatile(
        "mma.sync.aligned.m16n8k16.row.col.f16.f16.f16.f16 "
        "{%0,%1}, {%2,%3,%4,%5}, {%6,%7}, {%0,%1};"
        : "+r"(d[0]), "+r"(d[1])
        : "r"(a[0]), "r"(a[1]), "r"(a[2]), "r"(a[3]), "r"(b0), "r"(b1));
}

// ---------------- Kernel 1: merged prep (centers + embeddings) -> fp16 ----------------
#define PREP_CENTER_BLOCKS 512
__global__ void __launch_bounds__(256) prep_kernel(const float* __restrict__ centers,
                                                   const float* __restrict__ emb,
                                                   float* __restrict__ out) {
    const int bid = blockIdx.x;
    const int t = threadIdx.x;

    if (bid < PREP_CENTER_BLOCKS) {
        __shared__ float wss[8];
        const int row = bid;
        float4 v = reinterpret_cast<const float4*>(centers + (size_t)row * D_DIM)[t];
        float ss = v.x * v.x + v.y * v.y + v.z * v.z + v.w * v.w;
#pragma unroll
        for (int o = 16; o; o >>= 1) ss += __shfl_xor_sync(0xFFFFFFFFu, ss, o);
        if ((t & 31) == 0) wss[t >> 5] = ss;
        __syncthreads();
        if (t < 32) {
            float x = (t < 8) ? wss[t] : 0.f;
#pragma unroll
            for (int o = 4; o; o >>= 1) x += __shfl_xor_sync(0xFFFFFFFFu, x, o);
            if (t == 0) wss[0] = x;
        }
        __syncthreads();
        const float sc = 1.0f / fmaxf(sqrtf(wss[0]), EPS_F);

        __half2* orow = reinterpret_cast<__half2*>(g_cbf + (size_t)row * D_DIM);
        orow[t * 2]     = __floats2half2_rn(v.x * sc, v.y * sc);
        orow[t * 2 + 1] = __floats2half2_rn(v.z * sc, v.w * sc);

        if (row == 0 && t == 0) out[0] = 0.f;
        return;
    }

    // embeddings path
    const int lane = t & 31;
    const int wrp  = t >> 5;
    const int row  = (bid - PREP_CENTER_BLOCKS) * 8 + wrp;

    const float4* src = reinterpret_cast<const float4*>(emb + (size_t)row * D_DIM);
    float4 v[8];
    float ss = 0.f;
#pragma unroll
    for (int j = 0; j < 8; ++j) {
        v[j] = src[lane + j * 32];
        ss += v[j].x * v[j].x + v[j].y * v[j].y + v[j].z * v[j].z + v[j].w * v[j].w;
    }
#pragma unroll
    for (int o = 16; o; o >>= 1) ss += __shfl_xor_sync(0xFFFFFFFFu, ss, o);
    const float sc = 1.0f / (fmaxf(sqrtf(ss), EPS_F) * TAU_F);

    __half2* dst = reinterpret_cast<__half2*>(g_ebf + (size_t)row * D_DIM);
#pragma unroll
    for (int j = 0; j < 8; ++j) {
        dst[(lane + j * 32) * 2]     = __floats2half2_rn(v[j].x * sc, v[j].y * sc);
        dst[(lane + j * 32) * 2 + 1] = __floats2half2_rn(v[j].z * sc, v[j].w * sc);
    }
}

// ---------------- Kernel 2: fp16-acc GEMM, mbarrier pipeline (no block barrier) -------
// grid = 1024: mtile = bid>>1 (128 rows), chunk = bid&1 (256 centers)
// 8 warps 2(m)x4(n): warp tile 64 rows x 64 cols, acc 64 f16x2 regs
// SMEM: A 4x8192 @0; B 4x16384 @32768 -> 98304; mbar @98304 (64B); stats after.
#define A_STG     8192u
#define B_STG     16384u
#define OFF_A     0u
#define OFF_B     32768u
#define OFF_MBAR  98304u          // full[s] @ +s*16, empty[s] @ +s*16+8
#define OFF_MM    98432u          // 512 f
#define OFF_MS    100480u
#define OFF_MLV   102528u         // end 104576
#define SMEM_DYN  (104576 + 1024)

__global__ void __launch_bounds__(256, 2)
gemm_chunk_kernel(const long long* __restrict__ labels,
                  float* __restrict__ out) {
    extern __shared__ uint8_t dyn[];
    const uint32_t sb = smem_u32(dyn);
    const uint32_t base = (sb + 1023u) & ~1023u;
    uint8_t* gbase = dyn + (base - sb);

    float* sm_m  = reinterpret_cast<float*>(gbase + OFF_MM);
    float* sm_s  = reinterpret_cast<float*>(gbase + OFF_MS);
    float* sm_lv = reinterpret_cast<float*>(gbase + OFF_MLV);

    const int t     = threadIdx.x;
    const int lane  = t & 31;
    const int wid   = t >> 5;
    const int wm    = wid & 1;    // 64-row slice
    const int wn    = wid >> 1;   // 64-col slice
    const int bid   = blockIdx.x;
    const int mtile = bid >> 1;
    const int chunk = bid & 1;
    const int row0  = mtile * TILE_M;

    const uint32_t MB = base + OFF_MBAR;
#define FULLB(s)  (MB + (uint32_t)(s) * 16u)
#define EMPTYB(s) (MB + (uint32_t)(s) * 16u + 8u)

    if (t == 0) {
#pragma unroll
        for (int s = 0; s < 4; ++s) {
            MBARRIER_INIT(FULLB(s), 256);   // every thread cp-arrives
            MBARRIER_INIT(EMPTYB(s), 8);    // one arrive per warp
        }
    }
    __syncthreads();

    // loader mapping: 16B chunk c -> row = c>>2, ch = c&3 (64B rows)
    const int lr = t >> 2, lch = t & 3;
    uint32_t swA[2], swB[4];
#pragma unroll
    for (int i = 0; i < 2; ++i)
        swA[i] = SWZ64((uint32_t)((lr + i * 64) * 64 + lch * 16));
#pragma unroll
    for (int i = 0; i < 4; ++i)
        swB[i] = SWZ64((uint32_t)((lr + i * 64) * 64 + lch * 16));
    const __half* agp = g_ebf + (size_t)(row0 + lr) * D_DIM + lch * 8;
    const __half* bgp = g_cbf + (size_t)(chunk * CH_N + lr) * D_DIM + lch * 8;

    // issue half a slab: part 0 = A(both) + B0; part 1 = B1..B3
    auto issue_part = [&](int kb, int stg, int part) {
        const uint32_t Ad = base + OFF_A + (uint32_t)stg * A_STG;
        const uint32_t Bd = base + OFF_B + (uint32_t)stg * B_STG;
        if (part == 0) {
            cp16(Ad + swA[0], agp + kb * KSLAB);
            cp16(Ad + swA[1], agp + kb * KSLAB + (size_t)64 * D_DIM);
            cp16(Bd + swB[0], bgp + kb * KSLAB);
        } else {
#pragma unroll
            for (int i = 1; i < 4; ++i)
                cp16(Bd + swB[i], bgp + kb * KSLAB + (size_t)(i * 64) * D_DIM);
        }
    };

    uint32_t acc[4][8][2];
#pragma unroll
    for (int am = 0; am < 4; ++am)
#pragma unroll
        for (int nt = 0; nt < 8; ++nt) { acc[am][nt][0] = 0u; acc[am][nt][1] = 0u; }

    // ---- prologue: slabs 0..2 into stages 0..2; full-arrive after each slab's cps ----
#pragma unroll
    for (int s = 0; s < 3; ++s) {
        issue_part(s, s, 0); issue_part(s, s, 1);
        CP_MBAR_ARRIVE(FULLB(s));
    }

    const int rlow = lane & 15;
    const int bhi  = (lane >> 4) * 16;
    const int krot = wid & 1;     // per-warp k-step rotation (2 steps/slab)

    // Precomputed, loop-invariant swizzled ldsm offsets (ks=0 basis).
    uint32_t aoff[4], boff[4];
#pragma unroll
    for (int am = 0; am < 4; ++am)
        aoff[am] = SWZ64((uint32_t)((wm * 64 + am * 16 + rlow) * 64 + bhi));
#pragma unroll
    for (int p = 0; p < 4; ++p)
        boff[p] = SWZ64((uint32_t)((wn * 64 + p * 16 + rlow) * 64 + bhi));

#pragma unroll 1
    for (int kb = 0; kb < NSLABS; ++kb) {
        const int s = kb & 3;
        const uint32_t Ab = base + OFF_A + (uint32_t)s * A_STG;
        const uint32_t Bb = base + OFF_B + (uint32_t)s * B_STG;
        const int s3 = (kb + 3) & 3;
        const bool do_issue = (kb + 3 < NSLABS);

        // slab kb resident (all 256 threads' cp.async for it completed)
        MBARRIER_WAIT_PARITY(FULLB(s), (kb >> 2) & 1);

#pragma unroll
        for (int ksi = 0; ksi < 2; ++ksi) {
            const int ks = (ksi + krot) & 1;   // rotated k-step order
            if (ksi == 0 && do_issue) {
                // stage s3 free once slab kb-1 fully consumed (8 warp-arrives)
                if (kb >= 1) MBARRIER_WAIT_PARITY(EMPTYB(s3), ((kb - 1) >> 2) & 1);
                issue_part(kb + 3, s3, 0);
            }

            const uint32_t kx = (uint32_t)(ks << 5);
            uint32_t af[4][4], bf[4][4];
#pragma unroll
            for (int am = 0; am < 4; ++am)
                ldsm4(af[am], Ab + (aoff[am] ^ kx));
#pragma unroll
            for (int p = 0; p < 4; ++p)
                ldsm4(bf[p], Bb + (boff[p] ^ kx));

            if (ksi == 1) {
                if (do_issue) {
                    issue_part(kb + 3, s3, 1);
                    CP_MBAR_ARRIVE(FULLB(s3));   // arrive once this thread's cps land
                }
                if (lane == 0) MBARRIER_ARRIVE(EMPTYB(s));  // this warp done reading stage s
            }

#pragma unroll
            for (int am = 0; am < 4; ++am)
#pragma unroll
                for (int p = 0; p < 4; ++p) {
                    mma_h(acc[am][2 * p],     af[am], bf[p][0], bf[p][2]);
                    mma_h(acc[am][2 * p + 1], af[am], bf[p][1], bf[p][3]);
                }
        }
    }
    __syncthreads();

    // ---- per-warp partial softmax over its 64 cols (scale pre-folded) ----
    const int ql = lane >> 2, qc = lane & 3;
#pragma unroll
    for (int am = 0; am < 4; ++am) {
#pragma unroll
        for (int h = 0; h < 2; ++h) {
            const int r = wm * 64 + am * 16 + ql + 8 * h;
            const int lc = (int)labels[row0 + r];

            float m = -1e30f;
            float v[16];
#pragma unroll
            for (int nt = 0; nt < 8; ++nt) {
                const __half2 hv = *reinterpret_cast<const __half2*>(&acc[am][nt][h]);
                const float2 f2 = __half22float2(hv);
                v[nt * 2]     = f2.x;
                v[nt * 2 + 1] = f2.y;
                m = fmaxf(m, fmaxf(f2.x, f2.y));
            }
            m = fmaxf(m, __shfl_xor_sync(0xFFFFFFFFu, m, 1));
            m = fmaxf(m, __shfl_xor_sync(0xFFFFFFFFu, m, 2));

            float s = 0.f, lv = 0.f;
#pragma unroll
            for (int nt = 0; nt < 8; ++nt)
#pragma unroll
                for (int e = 0; e < 2; ++e) {
                    s += __expf(v[nt * 2 + e] - m);
                    const int col = chunk * CH_N + wn * 64 + nt * 8 + qc * 2 + e;
                    if (col == lc) lv = v[nt * 2 + e];
                }
            s  += __shfl_xor_sync(0xFFFFFFFFu, s, 1);
            s  += __shfl_xor_sync(0xFFFFFFFFu, s, 2);
            lv += __shfl_xor_sync(0xFFFFFFFFu, lv, 1);
            lv += __shfl_xor_sync(0xFFFFFFFFu, lv, 2);

            if (qc == 0) {
                sm_m[wn * 128 + r]  = m;
                sm_s[wn * 128 + r]  = s;
                sm_lv[wn * 128 + r] = lv;
            }
        }
    }
    __syncthreads();

    // ---- merge 4 warp-columns, write chunk partials ----
    if (t < TILE_M) {
        float M = -1e30f;
#pragma unroll
        for (int w = 0; w < 4; ++w) M = fmaxf(M, sm_m[w * 128 + t]);
        float S = 0.f, LV = 0.f;
#pragma unroll
        for (int w = 0; w < 4; ++w) {
            S  += sm_s[w * 128 + t] * __expf(sm_m[w * 128 + t] - M);
            LV += sm_lv[w * 128 + t];
        }
        const int gr = row0 + t;
        g_pm[chunk * N_ROWS + gr]  = M;
        g_ps[chunk * N_ROWS + gr]  = S;
        g_plv[chunk * N_ROWS + gr] = LV;
        __threadfence();          // publish partials before counter bump
    }
    __syncthreads();

    // ---- fused finalize: last chunk-CTA of this mtile merges & accumulates ----
    __shared__ int s_last;
    if (t == 0) {
        int old = atomicAdd(&g_cnt[mtile], 1);
        s_last = (old == NCHUNK - 1) ? 1 : 0;
    }
    __syncthreads();
    if (s_last) {
        __threadfence();          // acquire: other chunk's partials visible
        float loss = 0.f;
        if (t < TILE_M) {
            const int gr = row0 + t;
            float M = -1e30f;
#pragma unroll
            for (int c = 0; c < NCHUNK; ++c) M = fmaxf(M, g_pm[c * N_ROWS + gr]);
            float S = 0.f, LV = 0.f;
#pragma unroll
            for (int c = 0; c < NCHUNK; ++c) {
                S  += g_ps[c * N_ROWS + gr] * __expf(g_pm[c * N_ROWS + gr] - M);
                LV += g_plv[c * N_ROWS + gr];
            }
            loss = (M + logf(S)) - LV;
        }
#pragma unroll
        for (int o = 16; o; o >>= 1) loss += __shfl_xor_sync(0xFFFFFFFFu, loss, o);
        __shared__ float wsum[8];
        if ((t & 31) == 0) wsum[t >> 5] = loss;
        __syncthreads();
        if (t < 32) {
            float x = (t < 8) ? wsum[t] : 0.f;
#pragma unroll
            for (int o = 4; o; o >>= 1) x += __shfl_xor_sync(0xFFFFFFFFu, x, o);
            if (t == 0) {
                atomicAdd(out, x * (1.0f / (float)N_ROWS));
                g_cnt[mtile] = 0;   // self-reset for next graph replay
            }
        }
    }
}

// ---------------- Launch ----------------
extern "C" void kernel_launch(void* const* d_in, const int* in_sizes, int n_in,
                              void* d_out, int out_size) {
    const float* emb       = (const float*)d_in[0];
    const float* centers   = (const float*)d_in[1];
    const long long* label = (const long long*)d_in[2];
    float* out             = (float*)d_out;

    cudaFuncSetAttribute(gemm_chunk_kernel, cudaFuncAttributeMaxDynamicSharedMemorySize, SMEM_DYN);

    prep_kernel<<<PREP_CENTER_BLOCKS + N_ROWS / 8, 256>>>(centers, emb, out);
    gemm_chunk_kernel<<<(N_ROWS / TILE_M) * NCHUNK, 256, SMEM_DYN>>>(label, out);
}